// round 4
// baseline (speedup 1.0000x reference)
#include <cuda_runtime.h>

#define N_NODES 50000
#define N_EDGES 200000
#define OUTD 32
#define IN_SELF 128
#define EDGE_DIM 16

#define EDGE_BLOCKS 296
#define EDGE_THREADS 512

// Node GEMM tiling: block tile 128 nodes x 32 chans, K=160 in 5 chunks of 32.
// 256 threads, each owns a 4-node x 4-chan accumulator tile.
#define BN 128
#define KB 32
#define BNP 132
#define NT 256

// Scratch: agg [N_NODES*32] followed by deg [N_NODES] in one symbol (one memset)
__device__ float g_scratch[N_NODES * OUTD + N_NODES];

__device__ __forceinline__ void red_add_v4(float* ptr, float4 v) {
    asm volatile("red.global.add.v4.f32 [%0], {%1, %2, %3, %4};"
                 :: "l"(ptr), "f"(v.x), "f"(v.y), "f"(v.z), "f"(v.w)
                 : "memory");
}

// ---------------------------------------------------------------------------
// Edge kernel (unchanged): per-block Wsum reduction, 4 edges/warp,
// 8 lanes/edge, 4 channels/lane, vectorized RED.128 into agg.
// ---------------------------------------------------------------------------
__global__ void __launch_bounds__(EDGE_THREADS)
edge_kernel(const float* __restrict__ h_neigh,
            const float* __restrict__ edge_features,
            const float* __restrict__ W_edge,
            const float* __restrict__ b_edge,
            const int* __restrict__ src,
            const int* __restrict__ dst) {
    __shared__ __align__(16) float sW[EDGE_DIM * OUTD];
    __shared__ __align__(16) float sb[OUTD];
    {
        int t = threadIdx.x;
        int j = t >> 4, k = t & 15;
        float s = 0.f;
        #pragma unroll
        for (int i = 0; i < OUTD; i++)
            s += W_edge[(i * OUTD + j) * EDGE_DIM + k];
        sW[k * OUTD + j] = s;
        if (t < OUTD) {
            float s2 = 0.f;
            #pragma unroll
            for (int i = 0; i < OUTD; i++)
                s2 += b_edge[i * OUTD + t];
            sb[t] = s2;
        }
    }
    __syncthreads();

    float* g_agg = g_scratch;
    float* g_deg = g_scratch + N_NODES * OUTD;

    const int lane = threadIdx.x & 31;
    const int warp = threadIdx.x >> 5;
    const int g = lane >> 3;
    const int p = lane & 7;
    const int wpb = EDGE_THREADS >> 5;
    const int nwarps = EDGE_BLOCKS * wpb;
    const int NGROUPS = N_EDGES / 4;

    for (int grp = blockIdx.x * wpb + warp; grp < NGROUPS; grp += nwarps) {
        int e0 = grp * 4;
        int e = e0 + g;
        int s = src[e];
        int d = dst[e];

        float2 ef = *reinterpret_cast<const float2*>(
            &edge_features[e0 * EDGE_DIM + lane * 2]);

        float4 acc = *reinterpret_cast<const float4*>(&sb[4 * p]);
        #pragma unroll
        for (int k = 0; k < EDGE_DIM; k++) {
            float ek = __shfl_sync(0xffffffffu, (k & 1) ? ef.y : ef.x, k >> 1, 8);
            float4 w = *reinterpret_cast<const float4*>(&sW[k * OUTD + 4 * p]);
            acc.x = fmaf(ek, w.x, acc.x);
            acc.y = fmaf(ek, w.y, acc.y);
            acc.z = fmaf(ek, w.z, acc.z);
            acc.w = fmaf(ek, w.w, acc.w);
        }

        float4 hv = *reinterpret_cast<const float4*>(&h_neigh[s * OUTD + 4 * p]);
        float4 msg = make_float4(hv.x * acc.x, hv.y * acc.y,
                                 hv.z * acc.z, hv.w * acc.w);
        red_add_v4(&g_agg[d * OUTD + 4 * p], msg);
        if (p == 0) atomicAdd(&g_deg[d], 1.0f);
    }
}

// ---------------------------------------------------------------------------
// Node kernel: software-pipelined, double-buffered register-blocked GEMM.
//   out[n,c] = relu( X[n,:] . Wc[c,:] ),  X=[h_self | agg/deg], K=160.
// ---------------------------------------------------------------------------
__global__ void __launch_bounds__(NT, 3)
node_kernel(const float* __restrict__ h_self,
            const float* __restrict__ W_self,
            const float* __restrict__ W_neigh,
            float* __restrict__ out) {
    __shared__ __align__(16) float h_s[2][KB][BNP];
    __shared__ __align__(16) float w_s[2][KB][OUTD];
    __shared__ float sinv[BN];

    const float* g_agg = g_scratch;
    const float* g_deg = g_scratch + N_NODES * OUTD;

    const int t = threadIdx.x;
    const int nbase = blockIdx.x * BN;
    const int tn = t >> 3;   // 0..31 -> node quad
    const int tc = t & 7;    // 0..7  -> channel quad

    // indices for staging: 4 h-float4s per thread, 1 w-float4
    const int snode = t >> 3;        // base node for i-loop (idx = t + i*NT)
    const int skvec = t & 7;

    if (t < BN) {
        int gn = nbase + t;
        sinv[t] = (gn < N_NODES) ? 1.0f / fmaxf(g_deg[gn], 1.0f) : 0.f;
    }

    float4 hreg[4];
    float4 wreg;

    // ---- register-load chunk kc ----
    auto load_regs = [&](int kc) {
        #pragma unroll
        for (int i = 0; i < 4; i++) {
            int node = snode + i * (NT >> 3);   // +0,32,64,96
            int gn = nbase + node;
            float4 v = make_float4(0.f, 0.f, 0.f, 0.f);
            if (gn < N_NODES) {
                if (kc < 4) {
                    v = *reinterpret_cast<const float4*>(
                        &h_self[gn * IN_SELF + kc * KB + skvec * 4]);
                } else {
                    v = *reinterpret_cast<const float4*>(
                        &g_agg[gn * OUTD + skvec * 4]);
                    float iv = sinv[node];
                    v.x *= iv; v.y *= iv; v.z *= iv; v.w *= iv;
                }
            }
            hreg[i] = v;
        }
        {
            int chan = t >> 3;       // 0..31
            int kvec = t & 7;
            if (kc < 4)
                wreg = *reinterpret_cast<const float4*>(
                    &W_self[chan * IN_SELF + kc * KB + kvec * 4]);
            else
                wreg = *reinterpret_cast<const float4*>(
                    &W_neigh[chan * OUTD + kvec * 4]);
        }
    };

    // ---- store regs into smem buffer b (transposed) ----
    auto store_smem = [&](int b) {
        #pragma unroll
        for (int i = 0; i < 4; i++) {
            int node = snode + i * (NT >> 3);
            h_s[b][skvec * 4 + 0][node] = hreg[i].x;
            h_s[b][skvec * 4 + 1][node] = hreg[i].y;
            h_s[b][skvec * 4 + 2][node] = hreg[i].z;
            h_s[b][skvec * 4 + 3][node] = hreg[i].w;
        }
        {
            int chan = t >> 3;
            int kvec = t & 7;
            w_s[b][kvec * 4 + 0][chan] = wreg.x;
            w_s[b][kvec * 4 + 1][chan] = wreg.y;
            w_s[b][kvec * 4 + 2][chan] = wreg.z;
            w_s[b][kvec * 4 + 3][chan] = wreg.w;
        }
    };

    float acc[4][4];
    #pragma unroll
    for (int r = 0; r < 4; r++)
        #pragma unroll
        for (int c = 0; c < 4; c++) acc[r][c] = 0.f;

    // prologue (needs sinv visible before kc=4 load; that's 4 iters away,
    // but sync below also covers it)
    load_regs(0);
    __syncthreads();       // sinv ready (and smem free)
    store_smem(0);
    __syncthreads();

    #pragma unroll
    for (int kc = 0; kc < 5; kc++) {
        int b = kc & 1;
        if (kc < 4) load_regs(kc + 1);   // LDG issued before compute
        // ---- compute: 32 k-steps, 16 FMA each ----
        #pragma unroll
        for (int kk = 0; kk < KB; kk++) {
            float4 w = *reinterpret_cast<const float4*>(&w_s[b][kk][tc * 4]);
            float4 h = *reinterpret_cast<const float4*>(&h_s[b][kk][tn * 4]);
            acc[0][0] = fmaf(h.x, w.x, acc[0][0]);
            acc[0][1] = fmaf(h.x, w.y, acc[0][1]);
            acc[0][2] = fmaf(h.x, w.z, acc[0][2]);
            acc[0][3] = fmaf(h.x, w.w, acc[0][3]);
            acc[1][0] = fmaf(h.y, w.x, acc[1][0]);
            acc[1][1] = fmaf(h.y, w.y, acc[1][1]);
            acc[1][2] = fmaf(h.y, w.z, acc[1][2]);
            acc[1][3] = fmaf(h.y, w.w, acc[1][3]);
            acc[2][0] = fmaf(h.z, w.x, acc[2][0]);
            acc[2][1] = fmaf(h.z, w.y, acc[2][1]);
            acc[2][2] = fmaf(h.z, w.z, acc[2][2]);
            acc[2][3] = fmaf(h.z, w.w, acc[2][3]);
            acc[3][0] = fmaf(h.w, w.x, acc[3][0]);
            acc[3][1] = fmaf(h.w, w.y, acc[3][1]);
            acc[3][2] = fmaf(h.w, w.z, acc[3][2]);
            acc[3][3] = fmaf(h.w, w.w, acc[3][3]);
        }
        if (kc < 4) store_smem(1 - b);   // fill other buffer
        __syncthreads();
    }

    // ---- epilogue: relu + vectorized store ----
    #pragma unroll
    for (int r = 0; r < 4; r++) {
        int gn = nbase + tn * 4 + r;
        if (gn < N_NODES) {
            float4 o = make_float4(fmaxf(acc[r][0], 0.f), fmaxf(acc[r][1], 0.f),
                                   fmaxf(acc[r][2], 0.f), fmaxf(acc[r][3], 0.f));
            *reinterpret_cast<float4*>(&out[gn * OUTD + tc * 4]) = o;
        }
    }
}

extern "C" void kernel_launch(void* const* d_in, const int* in_sizes, int n_in,
                              void* d_out, int out_size) {
    const float* h_neigh       = (const float*)d_in[0];
    const float* h_self        = (const float*)d_in[1];
    const float* edge_features = (const float*)d_in[2];
    const float* W_edge        = (const float*)d_in[3];
    const float* b_edge        = (const float*)d_in[4];
    const float* W_self        = (const float*)d_in[5];
    const float* W_neigh       = (const float*)d_in[6];
    const int*   src           = (const int*)d_in[7];
    const int*   dst           = (const int*)d_in[8];
    float* out = (float*)d_out;

    void* scratch_ptr = nullptr;
    cudaGetSymbolAddress(&scratch_ptr, g_scratch);
    cudaMemsetAsync(scratch_ptr, 0, sizeof(float) * (N_NODES * OUTD + N_NODES), 0);

    edge_kernel<<<EDGE_BLOCKS, EDGE_THREADS>>>(h_neigh, edge_features,
                                               W_edge, b_edge, src, dst);

    int node_blocks = (N_NODES + BN - 1) / BN;  // 391
    node_kernel<<<node_blocks, NT>>>(h_self, W_self, W_neigh, out);
}